// round 9
// baseline (speedup 1.0000x reference)
#include <cuda_runtime.h>
#include <math_constants.h>

#define BB 512
#define TT 1024
#define KK 48

typedef unsigned long long ull;

__device__ __forceinline__ ull pack2(float lo, float hi) {
    return ((ull)__float_as_uint(hi) << 32) | (ull)__float_as_uint(lo);
}
__device__ __forceinline__ float ulo(ull v){ return __uint_as_float((unsigned)v); }
__device__ __forceinline__ float uhi(ull v){ return __uint_as_float((unsigned)(v >> 32)); }

#define FFMA2(d,a,b,c) asm("fma.rn.f32x2 %0, %1, %2, %3;" : "=l"(d) : "l"(a), "l"(b), "l"(c))
#define FADD2(d,a,b)   asm("add.rn.f32x2 %0, %1, %2;"     : "=l"(d) : "l"(a), "l"(b))

// ---------------------------------------------------------------------------
// One block (64 threads, 2 warps) per batch. Lane n owns OUTPUT state n
// (n >= 48: clamped duplicate of state 47, writes unread slots).
// Linear-space recurrence:
//   s_t[j] = (sum_i s_{t-1}[i] * exp(trans[j,i])) * exp(em[t,j]) / s_{t-1}[0]
//   C_t    = C_{t-1} + log(s_{t-1}[0])
// s_{t-1}[0] comes free from the chunk-0 LDS.128 every lane already performs,
// so there is NO shfl / stale-rescale machinery. Per warp per step: only
// 24 FFMA2 (one output per lane) -> half the fma-pipe issue of the
// 2-states-per-lane layout. Emissions: 3-stage pipeline
// (LDG group g+2 | exp of group g+1 | consume g).
// ---------------------------------------------------------------------------
__global__ void __launch_bounds__(64) crf_fused_kernel(
    const float* __restrict__ em,
    const int*   __restrict__ tags,
    const void*  __restrict__ mask,
    const float* __restrict__ trans,
    const float* __restrict__ startt,
    const float* __restrict__ endt,
    float*       __restrict__ out)
{
    const int b = blockIdx.x;
    const int n = threadIdx.x;             // 0..63
    const int w = n >> 5;                  // warp id
    const int o = (n < KK) ? n : (KK - 1); // owned output state (clamped)

    __shared__ __align__(16) float sh[2][64];
    __shared__ float red[2][2];            // [what][warp]

    // ---- sequence length (mask monotone prefix; dtype sniffed:
    //      mask[0,1] guaranteed true since lengths >= T/2) ----
    const unsigned char* mb = (const unsigned char*)mask;
    int cnt = 0;
    if (mb[1] | mb[2] | mb[3]) {
        const unsigned char* m = mb + b * TT;
        #pragma unroll
        for (int t = n; t < TT; t += 64) cnt += (m[t] != 0);
    } else {
        const unsigned int* m = (const unsigned int*)mask + b * TT;
        #pragma unroll
        for (int t = n; t < TT; t += 64) cnt += (m[t] != 0u);
    }
    #pragma unroll
    for (int oo = 16; oo; oo >>= 1) cnt += __shfl_xor_sync(0xffffffffu, cnt, oo);
    if ((n & 31) == 0) red[0][w] = (float)cnt;
    __syncthreads();
    const int len = (int)red[0][0] + (int)red[0][1];

    const size_t em_base = (size_t)b * TT * KK;

    // ---- numerator score (both warps, stride 64) ----
    float accw = 0.0f;
    {
        const int base = b * TT;
        for (int k = 0; k * 64 < len; k++) {
            int t = k * 64 + n;
            if (t >= 1 && t < len) {
                int cur  = tags[base + t];
                int prev = tags[base + t - 1];
                accw += em[em_base + (size_t)t * KK + cur] + trans[prev * KK + cur];
            }
        }
        #pragma unroll
        for (int oo = 16; oo; oo >>= 1) accw += __shfl_xor_sync(0xffffffffu, accw, oo);
    }
    __syncthreads();
    if ((n & 31) == 0) red[1][w] = accw;

    // ---- exp(transitions) row for the owned output state (packed f32x2) ----
    ull eT[24];
    #pragma unroll
    for (int i = 0; i < 24; i++)
        eT[i] = pack2(__expf(trans[o * KK + 2 * i]),
                      __expf(trans[o * KK + 2 * i + 1]));
    const float eend = __expf(endt[o]);

    // ---- init t = 0:  s_0[j] = exp(alpha0_j - alpha0_0),  C = alpha0_0 ----
    const float c0 = startt[0] + em[em_base + 0];   // broadcast load, all lanes
    float qme = __expf(startt[o] + em[em_base + o] - c0);
    sh[0][n] = (n < KK) ? qme : 0.0f;               // pad slots zero (unread)
    float C = c0;
    __syncthreads();

    // ---- emission pipeline: prime (scalar per lane) ----
    float EA[8], EB[8], R[8];
    #pragma unroll
    for (int s = 0; s < 8; s++) {               // exp for t = 1..8 (exposed once)
        int tt = 1 + s; tt = (tt < TT) ? tt : (TT - 1);
        EA[s] = __expf(em[em_base + (size_t)tt * KK + o]);
    }
    #pragma unroll
    for (int s = 0; s < 8; s++) {               // raw for t = 9..16
        int tt = 9 + s; tt = (tt < TT) ? tt : (TT - 1);
        R[s] = em[em_base + (size_t)tt * KK + o];
    }

#define STEP(RD, WR, EE) do {                                                  \
    const double2* P2 = (const double2*)sh[RD];                                \
    double2 p0 = P2[0];                                                        \
    float q0prev = ulo(__double_as_longlong(p0.x));  /* s_{t-1}[0], free */    \
    float r  = __fdividef(1.0f, q0prev);             /* off-chain-ish */       \
    float Er = (EE) * r;                                                       \
    ull A0=0,A1=0,A2=0,A3=0;                                                   \
    FFMA2(A0, __double_as_longlong(p0.x), eT[0], A0);                          \
    FFMA2(A1, __double_as_longlong(p0.y), eT[1], A1);                          \
    _Pragma("unroll")                                                          \
    for (int i = 1; i < 12; i += 2) {                                          \
        double2 qa = P2[i];                                                    \
        double2 qb = (i + 1 < 12) ? P2[i + 1] : make_double2(0.0, 0.0);        \
        FFMA2(A2, __double_as_longlong(qa.x), eT[2*i+0], A2);                  \
        FFMA2(A3, __double_as_longlong(qa.y), eT[2*i+1], A3);                  \
        if (i + 1 < 12) {                                                      \
            FFMA2(A0, __double_as_longlong(qb.x), eT[2*i+2], A0);              \
            FFMA2(A1, __double_as_longlong(qb.y), eT[2*i+3], A1);              \
        }                                                                      \
    }                                                                          \
    FADD2(A0, A0, A1); FADD2(A2, A2, A3); FADD2(A0, A0, A2);                   \
    float u = ulo(A0) + uhi(A0);                                               \
    C += __logf(q0prev);              /* scalar side chain */                  \
    qme = u * Er;                                                              \
    sh[WR][n] = (n < KK) ? qme : 0.0f;                                         \
    __syncthreads();                                                           \
} while (0)

    // group: ECUR consumed now; ENXT = exp(R) (loads from last group, landed);
    // R refilled for the group after next. t0 stays odd -> RD = s&1.
#define GROUP(ECUR, ENXT) do {                                                 \
    _Pragma("unroll")                                                          \
    for (int s = 0; s < 8; s++) ENXT[s] = __expf(R[s]);                        \
    _Pragma("unroll")                                                          \
    for (int s = 0; s < 8; s++) {                                              \
        int tt = t0 + 16 + s; tt = (tt < TT) ? tt : (TT - 1);                  \
        R[s] = em[em_base + (size_t)tt * KK + o];                              \
    }                                                                          \
    {                                                                          \
        const int tend = (t0 + 8 < len) ? (t0 + 8) : len;                      \
        _Pragma("unroll")                                                      \
        for (int s = 0; s < 8; s++) {                                          \
            if (t0 + s >= tend) break;                                         \
            if (s & 1) STEP(1, 0, ECUR[s]);                                    \
            else       STEP(0, 1, ECUR[s]);                                    \
        }                                                                      \
    }                                                                          \
    t0 += 8;                                                                   \
} while (0)

    int t0 = 1;
    while (t0 < len) {
        GROUP(EA, EB);
        if (t0 >= len) break;
        GROUP(EB, EA);
    }
#undef GROUP
#undef STEP

    // ---- out = score - (C + log( sum_j s_j * exp(end_j) )) ----
    float tot = (n < KK) ? qme * eend : 0.0f;
    #pragma unroll
    for (int oo = 16; oo; oo >>= 1) tot += __shfl_xor_sync(0xffffffffu, tot, oo);
    if ((n & 31) == 0) red[0][w] = tot;
    __syncthreads();

    if (n == 0) {
        const int base = b * TT;
        int tag0 = tags[base];
        float acc = red[1][0] + red[1][1];
        float score = startt[tag0] + em[em_base + tag0] + acc
                    + endt[tags[base + len - 1]];
        float tsum = red[0][0] + red[0][1];
        out[b] = score - (C + __logf(tsum));
    }
}

extern "C" void kernel_launch(void* const* d_in, const int* in_sizes, int n_in,
                              void* d_out, int out_size)
{
    const float* em    = (const float*)d_in[0];
    const int*   tags  = (const int*)d_in[1];
    const void*  mask  = d_in[2];
    const float* trans = (const float*)d_in[3];
    const float* stt   = (const float*)d_in[4];
    const float* ent   = (const float*)d_in[5];
    float*       out   = (float*)d_out;

    crf_fused_kernel<<<BB, 64>>>(em, tags, mask, trans, stt, ent, out);
}

// round 10
// speedup vs baseline: 1.1147x; 1.1147x over previous
#include <cuda_runtime.h>
#include <math_constants.h>

#define BB 512
#define TT 1024
#define KK 48

typedef unsigned long long ull;

__device__ __forceinline__ ull pack2(float lo, float hi) {
    ull d;
    asm("mov.b64 %0, {%1, %2};" : "=l"(d) : "f"(lo), "f"(hi));
    return d;
}
__device__ __forceinline__ float ulo(ull v){ return __uint_as_float((unsigned)v); }
__device__ __forceinline__ float uhi(ull v){ return __uint_as_float((unsigned)(v >> 32)); }

#define FFMA2(d,a,b,c) asm("fma.rn.f32x2 %0, %1, %2, %3;" : "=l"(d) : "l"(a), "l"(b), "l"(c))
#define FADD2(d,a,b)   asm("add.rn.f32x2 %0, %1, %2;"     : "=l"(d) : "l"(a), "l"(b))

// ---------------------------------------------------------------------------
// One block (32 threads, 1 warp) per batch. Lane l owns states 2l and 2l+1
// (lanes 24..31: zero rows). Forward recurrence in LINEAR space:
//   q_t[j] = (sum_i q_{t-1}[i] * exp(trans[j,i])) * exp(em[t,j]) / q_{t-1}[0]
//   C_t    = C_{t-1} + log(q_{t-1}[0])
// The state vector lives entirely in warp registers; the per-step exchange is
// 48 uniform-source shfl broadcasts (2 per pair) -> NO smem, NO barrier, NO
// stale rescale (q_{t-1}[0] is the very first broadcast). Emissions keep the
// 3-stage pipeline: LDG (group g+2) | exp of group g+1 | consume group g.
// ---------------------------------------------------------------------------
__global__ void __launch_bounds__(32) crf_fused_kernel(
    const float* __restrict__ em,
    const int*   __restrict__ tags,
    const void*  __restrict__ mask,
    const float* __restrict__ trans,
    const float* __restrict__ startt,
    const float* __restrict__ endt,
    float*       __restrict__ out)
{
    const int b  = blockIdx.x;
    const int l  = threadIdx.x;            // 0..31
    const int s0 = 2 * l, s1 = 2 * l + 1;
    const bool valid = (s0 < KK);          // l < 24
    const int e0 = valid ? s0 : (KK - 2);  // clamped pair base (8B aligned)

    // ---- sequence length (mask monotone prefix; dtype sniffed:
    //      mask[0,1] guaranteed true since lengths >= T/2) ----
    const unsigned char* mb = (const unsigned char*)mask;
    int cnt = 0;
    if (mb[1] | mb[2] | mb[3]) {
        const unsigned char* m = mb + b * TT;
        #pragma unroll
        for (int t = l; t < TT; t += 32) cnt += (m[t] != 0);
    } else {
        const unsigned int* m = (const unsigned int*)mask + b * TT;
        #pragma unroll
        for (int t = l; t < TT; t += 32) cnt += (m[t] != 0u);
    }
    #pragma unroll
    for (int o = 16; o; o >>= 1) cnt += __shfl_xor_sync(0xffffffffu, cnt, o);
    const int len = cnt;

    const size_t em_base = (size_t)b * TT * KK;

    // ---- numerator score ----
    float acc = 0.0f;
    {
        const int base = b * TT;
        for (int k = 0; k * 32 < len; k++) {
            int t = k * 32 + l;
            if (t >= 1 && t < len) {
                int cur  = tags[base + t];
                int prev = tags[base + t - 1];
                acc += em[em_base + (size_t)t * KK + cur] + trans[prev * KK + cur];
            }
        }
        #pragma unroll
        for (int o = 16; o; o >>= 1) acc += __shfl_xor_sync(0xffffffffu, acc, o);
    }

    // ---- exp(transitions) rows for both owned states (packed f32x2) ----
    ull eTa[24], eTb[24];
    #pragma unroll
    for (int i = 0; i < 24; i++) {
        eTa[i] = valid ? pack2(__expf(trans[s0 * KK + 2 * i]),
                               __expf(trans[s0 * KK + 2 * i + 1])) : 0ULL;
        eTb[i] = valid ? pack2(__expf(trans[s1 * KK + 2 * i]),
                               __expf(trans[s1 * KK + 2 * i + 1])) : 0ULL;
    }
    const float eend0 = valid ? __expf(endt[s0]) : 0.0f;
    const float eend1 = valid ? __expf(endt[s1]) : 0.0f;

    // ---- init t = 0 ----
    const float c0 = startt[0] + em[em_base + 0];   // alpha0[0], all lanes
    float q0v = valid ? __expf(startt[s0] + em[em_base + s0] - c0) : 0.0f;
    float q1v = valid ? __expf(startt[s1] + em[em_base + s1] - c0) : 0.0f;
    float C = c0;

    // ---- emission pipeline: prime ----
    float2 EA[8], EB[8], R[8];
    #pragma unroll
    for (int s = 0; s < 8; s++) {               // exp for t = 1..8 (exposed once)
        int tt = 1 + s; tt = (tt < TT) ? tt : (TT - 1);
        float2 v = *(const float2*)&em[em_base + (size_t)tt * KK + e0];
        EA[s] = make_float2(__expf(v.x), __expf(v.y));
    }
    #pragma unroll
    for (int s = 0; s < 8; s++) {               // raw for t = 9..16
        int tt = 9 + s; tt = (tt < TT) ? tt : (TT - 1);
        R[s] = *(const float2*)&em[em_base + (size_t)tt * KK + e0];
    }

    // one step, all-register: 48 uniform shfl broadcasts feed both dots
#define STEP(EE) do {                                                          \
    ull A0=0,A1=0,A2=0,A3=0,B0=0,B1=0,B2=0,B3=0;                               \
    float q0prev;                                                              \
    {   /* pair 0 first: its lo IS q_{t-1}[0] */                               \
        float xlo = __shfl_sync(0xffffffffu, q0v, 0);                          \
        float xhi = __shfl_sync(0xffffffffu, q1v, 0);                          \
        q0prev = xlo;                                                          \
        ull x = pack2(xlo, xhi);                                               \
        FFMA2(A0, x, eTa[0], A0);  FFMA2(B0, x, eTb[0], B0);                   \
    }                                                                          \
    float r  = __fdividef(1.0f, q0prev);   /* exact rescale, early */          \
    float Er0 = (EE).x * r;                                                    \
    float Er1 = (EE).y * r;                                                    \
    _Pragma("unroll")                                                          \
    for (int i = 1; i < 24; i++) {                                             \
        float xlo = __shfl_sync(0xffffffffu, q0v, i);                          \
        float xhi = __shfl_sync(0xffffffffu, q1v, i);                          \
        ull x = pack2(xlo, xhi);                                               \
        ull* A = (i & 3) == 0 ? &A0 : (i & 3) == 1 ? &A1 : (i & 3) == 2 ? &A2 : &A3; \
        ull* Bq = (i & 3) == 0 ? &B0 : (i & 3) == 1 ? &B1 : (i & 3) == 2 ? &B2 : &B3; \
        FFMA2(*A, x, eTa[i], *A);  FFMA2(*Bq, x, eTb[i], *Bq);                 \
    }                                                                          \
    FADD2(A0, A0, A1); FADD2(A2, A2, A3); FADD2(A0, A0, A2);                   \
    FADD2(B0, B0, B1); FADD2(B2, B2, B3); FADD2(B0, B0, B2);                   \
    float u0 = ulo(A0) + uhi(A0);                                              \
    float u1 = ulo(B0) + uhi(B0);                                              \
    C += __logf(q0prev);              /* scalar side chain */                  \
    q0v = u0 * Er0;                                                            \
    q1v = u1 * Er1;                                                            \
} while (0)

    // group: ECUR consumed now; ENXT = exp(R) (loads from last group, landed);
    // R refilled for the group after next.
#define GROUP(ECUR, ENXT) do {                                                 \
    _Pragma("unroll")                                                          \
    for (int s = 0; s < 8; s++)                                                \
        ENXT[s] = make_float2(__expf(R[s].x), __expf(R[s].y));                 \
    _Pragma("unroll")                                                          \
    for (int s = 0; s < 8; s++) {                                              \
        int tt = t0 + 16 + s; tt = (tt < TT) ? tt : (TT - 1);                  \
        R[s] = *(const float2*)&em[em_base + (size_t)tt * KK + e0];            \
    }                                                                          \
    {                                                                          \
        const int tend = (t0 + 8 < len) ? (t0 + 8) : len;                      \
        _Pragma("unroll")                                                      \
        for (int s = 0; s < 8; s++) {                                          \
            if (t0 + s >= tend) break;                                         \
            STEP(ECUR[s]);                                                     \
        }                                                                      \
    }                                                                          \
    t0 += 8;                                                                   \
} while (0)

    int t0 = 1;
    while (t0 < len) {
        GROUP(EA, EB);
        if (t0 >= len) break;
        GROUP(EB, EA);
    }
#undef GROUP
#undef STEP

    // ---- out = score - (C + log( sum_j q_j * exp(end_j) )) ----
    float tot = q0v * eend0 + q1v * eend1;
    #pragma unroll
    for (int o = 16; o; o >>= 1) tot += __shfl_xor_sync(0xffffffffu, tot, o);

    if (l == 0) {
        const int base = b * TT;
        int tag0 = tags[base];
        float score = startt[tag0] + em[em_base + tag0] + acc
                    + endt[tags[base + len - 1]];
        out[b] = score - (C + __logf(tot));
    }
}

extern "C" void kernel_launch(void* const* d_in, const int* in_sizes, int n_in,
                              void* d_out, int out_size)
{
    const float* em    = (const float*)d_in[0];
    const int*   tags  = (const int*)d_in[1];
    const void*  mask  = d_in[2];
    const float* trans = (const float*)d_in[3];
    const float* stt   = (const float*)d_in[4];
    const float* ent   = (const float*)d_in[5];
    float*       out   = (float*)d_out;

    crf_fused_kernel<<<BB, 32>>>(em, tags, mask, trans, stt, ent, out);
}

// round 11
// speedup vs baseline: 1.6073x; 1.4419x over previous
#include <cuda_runtime.h>
#include <math_constants.h>

#define BB 512
#define TT 1024
#define KK 48

typedef unsigned long long ull;

__device__ __forceinline__ ull pack2(float lo, float hi) {
    return ((ull)__float_as_uint(hi) << 32) | (ull)__float_as_uint(lo);
}
__device__ __forceinline__ float ulo(ull v){ return __uint_as_float((unsigned)v); }
__device__ __forceinline__ float uhi(ull v){ return __uint_as_float((unsigned)(v >> 32)); }

#define FFMA2(d,a,b,c) asm("fma.rn.f32x2 %0, %1, %2, %3;" : "=l"(d) : "l"(a), "l"(b), "l"(c))
#define FADD2(d,a,b)   asm("add.rn.f32x2 %0, %1, %2;"     : "=l"(d) : "l"(a), "l"(b))

// ---------------------------------------------------------------------------
// One block (32 threads, 1 warp) per batch. Lane l owns states 2l and 2l+1
// (lanes 24..31: zero rows). Forward recurrence in LINEAR space:
//   q_t[j] = (sum_i q_{t-1}[i] * exp(trans[j,i])) * exp(em[t,j]) / q_{t-1}[0]
//   C via xprod: xprod *= q_{t-1}[0] each step; C += log(xprod) per group.
// q_{t-1}[0] is the low word of the first LDS.128 chunk (free) -> exact
// rescale, no shfl, no per-step logf. Emissions: 3-stage pipeline
// (LDG group g+2 | exp of group g+1 | consume g).
// ---------------------------------------------------------------------------
__global__ void __launch_bounds__(32) crf_fused_kernel(
    const float* __restrict__ em,
    const int*   __restrict__ tags,
    const void*  __restrict__ mask,
    const float* __restrict__ trans,
    const float* __restrict__ startt,
    const float* __restrict__ endt,
    float*       __restrict__ out)
{
    const int b  = blockIdx.x;
    const int l  = threadIdx.x;            // 0..31
    const int s0 = 2 * l, s1 = 2 * l + 1;
    const bool valid = (s0 < KK);          // l < 24
    const int e0 = valid ? s0 : (KK - 2);  // clamped pair base (8B aligned)

    __shared__ __align__(16) float sh[2][64];

    // ---- sequence length (mask monotone prefix; dtype sniffed:
    //      mask[0,1] guaranteed true since lengths >= T/2) ----
    const unsigned char* mb = (const unsigned char*)mask;
    int cnt = 0;
    if (mb[1] | mb[2] | mb[3]) {
        const unsigned char* m = mb + b * TT;
        #pragma unroll
        for (int t = l; t < TT; t += 32) cnt += (m[t] != 0);
    } else {
        const unsigned int* m = (const unsigned int*)mask + b * TT;
        #pragma unroll
        for (int t = l; t < TT; t += 32) cnt += (m[t] != 0u);
    }
    #pragma unroll
    for (int o = 16; o; o >>= 1) cnt += __shfl_xor_sync(0xffffffffu, cnt, o);
    const int len = cnt;

    const size_t em_base = (size_t)b * TT * KK;

    // ---- numerator score ----
    float acc = 0.0f;
    {
        const int base = b * TT;
        for (int k = 0; k * 32 < len; k++) {
            int t = k * 32 + l;
            if (t >= 1 && t < len) {
                int cur  = tags[base + t];
                int prev = tags[base + t - 1];
                acc += em[em_base + (size_t)t * KK + cur] + trans[prev * KK + cur];
            }
        }
        #pragma unroll
        for (int o = 16; o; o >>= 1) acc += __shfl_xor_sync(0xffffffffu, acc, o);
    }

    // ---- exp(transitions) rows for both owned states (packed f32x2) ----
    ull eTa[24], eTb[24];
    #pragma unroll
    for (int i = 0; i < 24; i++) {
        eTa[i] = valid ? pack2(__expf(trans[s0 * KK + 2 * i]),
                               __expf(trans[s0 * KK + 2 * i + 1])) : 0ULL;
        eTb[i] = valid ? pack2(__expf(trans[s1 * KK + 2 * i]),
                               __expf(trans[s1 * KK + 2 * i + 1])) : 0ULL;
    }
    const float eend0 = valid ? __expf(endt[s0]) : 0.0f;
    const float eend1 = valid ? __expf(endt[s1]) : 0.0f;

    // ---- init t = 0 ----
    const float c0 = startt[0] + em[em_base + 0];   // alpha0[0], all lanes
    float q0v = valid ? __expf(startt[s0] + em[em_base + s0] - c0) : 0.0f;
    float q1v = valid ? __expf(startt[s1] + em[em_base + s1] - c0) : 0.0f;
    ((float2*)sh[0])[l] = make_float2(q0v, q1v);
    float C = c0, xprod = 1.0f;
    __syncthreads();

    // ---- emission pipeline: prime ----
    float2 EA[8], EB[8], R[8];
    #pragma unroll
    for (int s = 0; s < 8; s++) {               // exp for t = 1..8 (exposed once)
        int tt = 1 + s; tt = (tt < TT) ? tt : (TT - 1);
        float2 v = *(const float2*)&em[em_base + (size_t)tt * KK + e0];
        EA[s] = make_float2(__expf(v.x), __expf(v.y));
    }
    #pragma unroll
    for (int s = 0; s < 8; s++) {               // raw for t = 9..16
        int tt = 9 + s; tt = (tt < TT) ? tt : (TT - 1);
        R[s] = *(const float2*)&em[em_base + (size_t)tt * KK + e0];
    }

#define STEP(RD, WR, EE) do {                                                  \
    const double2* P2 = (const double2*)sh[RD];                                \
    double2 p0 = P2[0];                                                        \
    float q0prev = ulo(__double_as_longlong(p0.x));  /* q_{t-1}[0], free */    \
    float r = __fdividef(1.0f, q0prev);   /* ready ~50cyc, used ~150cyc */     \
    ull A0=0,A1=0,A2=0,A3=0,B0=0,B1=0,B2=0,B3=0;                               \
    {                                                                          \
        ull xa = __double_as_longlong(p0.x), xb = __double_as_longlong(p0.y);  \
        FFMA2(A0, xa, eTa[0], A0);  FFMA2(A1, xb, eTa[1], A1);                 \
        FFMA2(B0, xa, eTb[0], B0);  FFMA2(B1, xb, eTb[1], B1);                 \
    }                                                                          \
    _Pragma("unroll")                                                          \
    for (int i = 1; i < 12; i++) {                                             \
        double2 q = P2[i];                                                     \
        ull xa = __double_as_longlong(q.x), xb = __double_as_longlong(q.y);    \
        if (i & 1) {                                                           \
            FFMA2(A2, xa, eTa[2*i+0], A2);  FFMA2(A3, xb, eTa[2*i+1], A3);     \
            FFMA2(B2, xa, eTb[2*i+0], B2);  FFMA2(B3, xb, eTb[2*i+1], B3);     \
        } else {                                                               \
            FFMA2(A0, xa, eTa[2*i+0], A0);  FFMA2(A1, xb, eTa[2*i+1], A1);     \
            FFMA2(B0, xa, eTb[2*i+0], B0);  FFMA2(B1, xb, eTb[2*i+1], B1);     \
        }                                                                      \
    }                                                                          \
    FADD2(A0, A0, A1); FADD2(A2, A2, A3); FADD2(A0, A0, A2);                   \
    FADD2(B0, B0, B1); FADD2(B2, B2, B3); FADD2(B0, B0, B2);                   \
    float u0 = ulo(A0) + uhi(A0);                                              \
    float u1 = ulo(B0) + uhi(B0);                                              \
    xprod *= q0prev;                  /* FMUL side chain (log deferred) */     \
    q0v = u0 * (EE).x * r;                                                     \
    q1v = u1 * (EE).y * r;                                                     \
    ((float2*)sh[WR])[l] = make_float2(q0v, q1v);                              \
    __syncthreads();                  /* nw=1 BAR, ~3 cyc */                   \
} while (0)

    // group: ECUR consumed now; ENXT = exp(R) (loads from last group, landed);
    // R refilled for the group after next. t0 stays odd -> RD = s&1.
#define GROUP(ECUR, ENXT) do {                                                 \
    _Pragma("unroll")                                                          \
    for (int s = 0; s < 8; s++)                                                \
        ENXT[s] = make_float2(__expf(R[s].x), __expf(R[s].y));                 \
    _Pragma("unroll")                                                          \
    for (int s = 0; s < 8; s++) {                                              \
        int tt = t0 + 16 + s; tt = (tt < TT) ? tt : (TT - 1);                  \
        R[s] = *(const float2*)&em[em_base + (size_t)tt * KK + e0];            \
    }                                                                          \
    {                                                                          \
        const int tend = (t0 + 8 < len) ? (t0 + 8) : len;                      \
        _Pragma("unroll")                                                      \
        for (int s = 0; s < 8; s++) {                                          \
            if (t0 + s >= tend) break;                                         \
            if (s & 1) STEP(1, 0, ECUR[s]);                                    \
            else       STEP(0, 1, ECUR[s]);                                    \
        }                                                                      \
    }                                                                          \
    C += __logf(xprod);               /* flush: one MUFU per 8 steps */        \
    xprod = 1.0f;                                                              \
    t0 += 8;                                                                   \
} while (0)

    int t0 = 1;
    while (t0 < len) {
        GROUP(EA, EB);
        if (t0 >= len) break;
        GROUP(EB, EA);
    }
#undef GROUP
#undef STEP

    // ---- out = score - (C + log( sum_j q_j * exp(end_j) )) ----
    float tot = q0v * eend0 + q1v * eend1;
    #pragma unroll
    for (int o = 16; o; o >>= 1) tot += __shfl_xor_sync(0xffffffffu, tot, o);

    if (l == 0) {
        const int base = b * TT;
        int tag0 = tags[base];
        float score = startt[tag0] + em[em_base + tag0] + acc
                    + endt[tags[base + len - 1]];
        out[b] = score - (C + __logf(tot));
    }
}

extern "C" void kernel_launch(void* const* d_in, const int* in_sizes, int n_in,
                              void* d_out, int out_size)
{
    const float* em    = (const float*)d_in[0];
    const int*   tags  = (const int*)d_in[1];
    const void*  mask  = d_in[2];
    const float* trans = (const float*)d_in[3];
    const float* stt   = (const float*)d_in[4];
    const float* ent   = (const float*)d_in[5];
    float*       out   = (float*)d_out;

    crf_fused_kernel<<<BB, 32>>>(em, tags, mask, trans, stt, ent, out);
}